// round 1
// baseline (speedup 1.0000x reference)
#include <cuda_runtime.h>
#include <math.h>

#define Nn   4
#define MA   256
#define NFS  128
#define KK   8
#define HID  256
#define OUTD 32
#define RCf  5.0f
#define PIf  3.14159265358979323846f
#define ROWS (Nn*MA)   // 1024 atoms total

// ---------------- scratch (device globals; no allocation allowed) ----------
__device__ float g_a[ROWS];              // h . Wa[:128]
__device__ float g_b[ROWS];              // h . Wa[128:]
__device__ float g_p[ROWS*HID];          // h @ Wp1[:128,:]
__device__ float g_q[ROWS*HID];          // h @ Wp1[128:,:]
__device__ float g_att[ROWS*KK];         // top-k attention values (normalized)
__device__ int   g_idx[ROWS*KK];         // top-k neighbor indices
__device__ float g_dvk[ROWS*KK*3];       // normalized direction vectors

// ---------------- kernel A: per-atom projections ---------------------------
// grid = ROWS/8 blocks, 256 threads. Each block: 8 atom rows.
// thread t owns hidden column t; 16 register accumulators.
__global__ void kA(const float* __restrict__ h,
                   const float* __restrict__ Wp1,
                   const float* __restrict__ Wa) {
    __shared__ float hs[8*NFS];
    const int t = threadIdx.x;
    const int row0 = blockIdx.x * 8;
    for (int i = t; i < 8*NFS; i += 256) hs[i] = h[(size_t)row0*NFS + i];
    __syncthreads();

    float accp[8], accq[8];
#pragma unroll
    for (int r = 0; r < 8; r++) { accp[r] = 0.f; accq[r] = 0.f; }

#pragma unroll 4
    for (int f = 0; f < NFS; f++) {
        const float wt = Wp1[f*HID + t];
        const float wb = Wp1[(NFS+f)*HID + t];
#pragma unroll
        for (int r = 0; r < 8; r++) {
            const float hv = hs[r*NFS + f];
            accp[r] = fmaf(hv, wt, accp[r]);
            accq[r] = fmaf(hv, wb, accq[r]);
        }
    }
#pragma unroll
    for (int r = 0; r < 8; r++) {
        g_p[(size_t)(row0+r)*HID + t] = accp[r];
        g_q[(size_t)(row0+r)*HID + t] = accq[r];
    }

    // a,b: warp w handles atom row w
    const int w = t >> 5, lane = t & 31;
    float sa = 0.f, sb = 0.f;
    for (int f = lane; f < NFS; f += 32) {
        const float hv = hs[w*NFS + f];
        sa = fmaf(hv, Wa[f],      sa);
        sb = fmaf(hv, Wa[NFS+f],  sb);
    }
#pragma unroll
    for (int off = 16; off; off >>= 1) {
        sa += __shfl_down_sync(0xffffffffu, sa, off);
        sb += __shfl_down_sync(0xffffffffu, sb, off);
    }
    if (lane == 0) { g_a[row0+w] = sa; g_b[row0+w] = sb; }
}

// ---------------- kernel B: attention + exact top-K ------------------------
// grid = ROWS (one block per (n,i)), 256 threads (thread j = candidate atom).
__global__ void kB(const int*   __restrict__ z,
                   const float* __restrict__ r,
                   const float* __restrict__ ba) {
    const int row = blockIdx.x;
    const int n = row / MA, i = row % MA;
    const int j = threadIdx.x;

    __shared__ float srx[MA], sry[MA], srz[MA];
    __shared__ int   sm[MA];
    __shared__ float red[256];
    __shared__ unsigned long long sk[256];

    srx[j] = r[(size_t)(n*MA + j)*3 + 0];
    sry[j] = r[(size_t)(n*MA + j)*3 + 1];
    srz[j] = r[(size_t)(n*MA + j)*3 + 2];
    sm[j]  = (z[n*MA + j] > -1) ? 1 : 0;
    __syncthreads();

    const float dx = srx[j] - srx[i];
    const float dy = sry[j] - sry[i];
    const float dz = srz[j] - srz[i];
    const float d  = sqrtf(dx*dx + dy*dy + dz*dz);

    const float mask = (sm[i] && sm[j] && (j != i)) ? 1.f : 0.f;
    float cf = 0.5f * (cosf(PIf * fminf(d, RCf) / RCf) + 1.f);
    if (i == j) cf -= 1.f;   // - eye
    cf *= mask;

    const float score = g_a[row] + cf * g_b[n*MA + j] + ba[0];
    const float g = (mask > 0.f) ? expf(score) : 0.f;   // exp(score*mask)-(1-mask)

    // block sum of g
    red[j] = g; __syncthreads();
#pragma unroll
    for (int s = 128; s; s >>= 1) { if (j < s) red[j] += red[j+s]; __syncthreads(); }
    const float sumg = red[0];
    __syncthreads();

    float v = g / fmaxf(sumg, 1e-8f);   // normalized attention (>= 0)
    bool removed = false;

    for (int k = 0; k < KK; k++) {
        // key packs (value desc, index asc-on-tie); v>=0 so float bits are monotone
        unsigned long long key = removed ? 0ULL
            : ((unsigned long long)__float_as_uint(v) << 32) | (unsigned)(MA - 1 - j);
        sk[j] = key; __syncthreads();
#pragma unroll
        for (int s = 128; s; s >>= 1) {
            if (j < s) { unsigned long long o = sk[j+s]; if (o > sk[j]) sk[j] = o; }
            __syncthreads();
        }
        const unsigned long long best = sk[0];
        const int bj = MA - 1 - (int)(best & 0xffffffffu);
        if (j == bj && !removed) {
            g_att[row*KK + k] = v;
            g_idx[row*KK + k] = j;
            const float nrm = fmaxf(d, 1e-4f);   // ||dvk|| == d
            g_dvk[(size_t)(row*KK + k)*3 + 0] = dx / nrm;
            g_dvk[(size_t)(row*KK + k)*3 + 1] = dy / nrm;
            g_dvk[(size_t)(row*KK + k)*3 + 2] = dz / nrm;
            removed = true;
        }
        __syncthreads();
    }
}

// ---------------- kernel C: fused MLP + directional output -----------------
// grid = ROWS, 256 threads per block (one block per (n,i)).
__global__ void kC(const float* __restrict__ bp1,
                   const float* __restrict__ Wp2,
                   const float* __restrict__ bp2,
                   float*       __restrict__ cout) {
    const int row = blockIdx.x;
    const int t = threadIdx.x;
    const int n = row / MA;

    __shared__ float pi_s[HID];
    __shared__ float hid[KK][HID];
    __shared__ float satt[KK];
    __shared__ int   sidx[KK];
    __shared__ float sdvk[KK*3];

    pi_s[t] = g_p[(size_t)row*HID + t];
    if (t < KK)   { satt[t] = g_att[row*KK + t]; sidx[t] = g_idx[row*KK + t]; }
    if (t < KK*3) { sdvk[t] = g_dvk[(size_t)row*KK*3 + t]; }
    const float b1 = bp1[t];
    __syncthreads();

#pragma unroll
    for (int k = 0; k < KK; k++) {
        const int jn = sidx[k];
        const float x = fmaf(satt[k], pi_s[t] + g_q[(size_t)(n*MA + jn)*HID + t], b1);
        hid[k][t] = x / (1.f + expf(-x));   // silu
    }
    __syncthreads();

    const int k = t >> 5;   // 0..7
    const int o = t & 31;   // 0..31
    float acc = bp2[o];
    const float* hk = hid[k];
#pragma unroll 8
    for (int tt = 0; tt < HID; tt++)
        acc = fmaf(hk[tt], Wp2[tt*OUTD + o], acc);

    const float d0 = sdvk[k*3+0], d1 = sdvk[k*3+1], d2 = sdvk[k*3+2];
    const size_t base = ((size_t)(row*KK + k)*OUTD + o) * 3;
    cout[base+0] = acc * d0;
    cout[base+1] = acc * d1;
    cout[base+2] = acc * d2;
}

// ---------------- kernel D: tuple prefix (z as float, then r) --------------
__global__ void kD(const int* __restrict__ z, const float* __restrict__ r,
                   float* __restrict__ out) {
    const int t = blockIdx.x * blockDim.x + threadIdx.x;
    if (t < ROWS)     out[t] = (float)z[t];
    if (t < ROWS*3)   out[ROWS + t] = r[t];
}

// ---------------------------------------------------------------------------
extern "C" void kernel_launch(void* const* d_in, const int* in_sizes, int n_in,
                              void* d_out, int out_size) {
    const int*   z   = (const int*)  d_in[0];
    const float* r   = (const float*)d_in[1];
    const float* h   = (const float*)d_in[2];
    const float* Wa  = (const float*)d_in[3];
    const float* ba  = (const float*)d_in[4];
    const float* Wp1 = (const float*)d_in[5];
    const float* bp1 = (const float*)d_in[6];
    const float* Wp2 = (const float*)d_in[7];
    const float* bp2 = (const float*)d_in[8];

    float* out = (float*)d_out;
    const int CSZ = Nn*MA*KK*OUTD*3;          // 786432
    const int PREF = ROWS + ROWS*3;           // 4096 (z + r)
    const bool has_prefix = (out_size == CSZ + PREF);
    float* cout = has_prefix ? (out + PREF) : out;

    kA<<<ROWS/8, 256>>>(h, Wp1, Wa);
    kB<<<ROWS,   256>>>(z, r, ba);
    kC<<<ROWS,   256>>>(bp1, Wp2, bp2, cout);
    if (has_prefix) kD<<<(ROWS*3 + 255)/256, 256>>>(z, r, out);
}